// round 4
// baseline (speedup 1.0000x reference)
#include <cuda_runtime.h>
#include <math_constants.h>

// Problem constants
#define KS     7
#define HALF   3
#define B_DIM  32
#define C_DIM  64
#define L_DIM  4096
#define I_DIM  (L_DIM / 2)       // 2048 outputs per row
#define ROWS_PER_BLK 4
#define NTHREADS 256

// Per-block table range: k in [s0, s0+4097]  (4098 entries)
#define E_N   4098
// f window: f_flat[s0-3 .. s0+4100]  (4104 floats)
#define F_N   4104

// Padded smem index for the dilation table (kills stride-8 bank conflicts)
#define PD(e) ((e) + ((e) >> 5))

// ---------------------------------------------------------------------------
// Fully fused kernel. Block q owns rows r = 4q..4q+3 (same b, consecutive c).
// out[b,c,i] = dil(s + 2i), s = b + c; valid tap z of dil(k) = f_flat[k+z] + h
// with h[c',z] = -(z^2)/(4*t[c']), c' = k>>12, validity 0 <= (k&4095)+z < L.
// ---------------------------------------------------------------------------
__global__ void __launch_bounds__(NTHREADS) pp_fused_kernel(
        const float* __restrict__ f,
        const float* __restrict__ t,
        float4* __restrict__ out) {
    __shared__ float fwin[F_N];
    __shared__ float dwin[E_N + (E_N >> 5) + 8];

    const int tid = threadIdx.x;
    const int q   = blockIdx.x;
    const int b   = q >> 4;                 // (4q) >> 6
    const int cb  = (q << 2) & (C_DIM - 1); // (4q) & 63
    const int s0  = b + cb;                 // base flat offset, <= 91

    // ---- Stage f window (coalesced, guarded low edge) ----
    #pragma unroll
    for (int x = tid; x < F_N; x += NTHREADS) {
        int g = s0 - 3 + x;                 // max 91-3+4103 = 4191 < 8192
        fwin[x] = (g >= 0) ? __ldg(&f[g]) : 0.0f;
    }

    // ---- Hoisted h values (exact same rounding as reference: -(z^2)/(4t)) ----
    float d0 = 4.0f * __ldg(&t[0]);
    float d1 = 4.0f * __ldg(&t[1]);
    float h1_0 = -1.0f / d0, h4_0 = -4.0f / d0, h9_0 = -9.0f / d0;
    float h1_1 = -1.0f / d1, h4_1 = -4.0f / d1, h9_1 = -9.0f / d1;

    __syncthreads();

    // ---- Compute dilation table: dil(s0 + e), e in [0, 4098) ----
    #pragma unroll
    for (int e = tid; e < E_N; e += NTHREADS) {
        int k  = s0 + e;
        int l0 = k & (L_DIM - 1);
        bool c1 = (k >> 12) != 0;
        float h1 = c1 ? h1_1 : h1_0;
        float h4 = c1 ? h4_1 : h4_0;
        float h9 = c1 ? h9_1 : h9_0;

        const float* w = &fwin[e + HALF];   // w[z] = f_flat[k+z]
        float m = w[0];                                         // z = 0
        m = fmaxf(m, (l0 >= 1)          ? w[-1] + h1 : -CUDART_INF_F);
        m = fmaxf(m, (l0 <  L_DIM - 1)  ? w[ 1] + h1 : -CUDART_INF_F);
        m = fmaxf(m, (l0 >= 2)          ? w[-2] + h4 : -CUDART_INF_F);
        m = fmaxf(m, (l0 <  L_DIM - 2)  ? w[ 2] + h4 : -CUDART_INF_F);
        m = fmaxf(m, (l0 >= 3)          ? w[-3] + h9 : -CUDART_INF_F);
        m = fmaxf(m, (l0 <  L_DIM - 3)  ? w[ 3] + h9 : -CUDART_INF_F);

        dwin[PD(e)] = m;
    }

    __syncthreads();

    // ---- Emit 4 rows x 512 float4 (2048 float4 / block, 8 per thread) ----
    #pragma unroll
    for (int w = 0; w < 8; ++w) {
        int u  = w * NTHREADS + tid;        // 0..2047
        int rr = u >> 9;                    // local row 0..3
        int i4 = u & (I_DIM / 4 - 1);       // float4 index in row
        int e0 = rr + (i4 << 3);            // element e for i = 4*i4
        float4 r;
        r.x = dwin[PD(e0)];
        r.y = dwin[PD(e0 + 2)];
        r.z = dwin[PD(e0 + 4)];
        r.w = dwin[PD(e0 + 6)];
        out[((q << 2) + rr) * (I_DIM / 4) + i4] = r;
    }
}

extern "C" void kernel_launch(void* const* d_in, const int* in_sizes, int n_in,
                              void* d_out, int out_size) {
    const float* f = (const float*)d_in[0];   // [32, 64, 4096] float32
    const float* t = (const float*)d_in[1];   // [64] float32
    float4* out = (float4*)d_out;             // [32, 64, 2048] float32

    int nblocks = (B_DIM * C_DIM) / ROWS_PER_BLK;   // 512
    pp_fused_kernel<<<nblocks, NTHREADS>>>(f, t, out);
}

// round 5
// speedup vs baseline: 1.7895x; 1.7895x over previous
#include <cuda_runtime.h>
#include <math_constants.h>

// Problem constants
#define KS       7
#define HALF     3
#define B_DIM    32
#define C_DIM    64
#define L_DIM    4096
#define I_DIM    (L_DIM / 2)
#define TABLE_N  4189            // max flat index b+c+2i = 31+63+2*2047 = 4188

// Alignment-replicated, parity-deinterleaved dilation tables.
// tabP[m] = dil(2m + p).  Float view: g_tabA[p][a][m] = tabP[m + a], so the
// read tabP[(s>>1) + i] with (s>>1) = 4q + a is the ALIGNED float4
// g_tabA[p][a][q + i/4] whenever i % 4 == 0.
__device__ float4 g_tabA[2][4][544];   // 2176 floats per copy

// ---------------------------------------------------------------------------
// Kernel A: dilation for flat indices 0..4188, written to all 8 copies.
// flat k -> (b=0, c'=k>>12, l'=k&4095); dil = max_j f[0,c',l'+j-3] + h[c',j]
// h[c,j] = -(j-3)^2 / (4*t[c]); -inf padding at l' borders.
// ---------------------------------------------------------------------------
__global__ void pp_table_kernel(const float* __restrict__ f,
                                const float* __restrict__ t) {
    int k = blockIdx.x * blockDim.x + threadIdx.x;
    if (k >= TABLE_N) return;
    int c0 = k >> 12;               // 0 or 1
    int l0 = k & (L_DIM - 1);
    float denom = 4.0f * __ldg(&t[c0]);
    const float* frow = f + c0 * L_DIM;   // batch 0

    float m = -CUDART_INF_F;
    #pragma unroll
    for (int j = 0; j < KS; ++j) {
        int z = j - HALF;
        int p = l0 + z;
        float h = -(float)(z * z) / denom;
        if (p >= 0 && p < L_DIM)
            m = fmaxf(m, __ldg(&frow[p]) + h);
    }

    int par = k & 1;
    int idx = k >> 1;               // index within parity table, <= 2094
    #pragma unroll
    for (int a = 0; a < 4; ++a) {
        if (idx >= a)
            reinterpret_cast<float*>(g_tabA[par][a])[idx - a] = m;
    }
}

// ---------------------------------------------------------------------------
// Kernel B: out[b,c,i] = dil(s + 2i), s = b + c.
// 512 blocks x 256 threads; each thread owns 8 float4 of ONE row:
// table pointer computed once, 8 front-batched LDG.128 (MLP=8), then
// 8 coalesced STG.128. Tables (70 KB) are L1/L2-hot.
// ---------------------------------------------------------------------------
__global__ void __launch_bounds__(256) pp_gather_kernel(float4* __restrict__ out) {
    const int tid = threadIdx.x;
    const int row = (blockIdx.x << 2) + (tid >> 6);   // global (b,c) row
    const int s   = (row >> 6) + (row & (C_DIM - 1)); // b + c
    const int hs  = s >> 1;
    const float4* __restrict__ tab = g_tabA[s & 1][hs & 3] + (hs >> 2);
    const int i0  = tid & 63;                         // float4 lane in row
    float4* __restrict__ orow = out + row * (I_DIM / 4);

    float4 r[8];
    #pragma unroll
    for (int w = 0; w < 8; ++w)
        r[w] = __ldg(&tab[i0 + (w << 6)]);
    #pragma unroll
    for (int w = 0; w < 8; ++w)
        orow[i0 + (w << 6)] = r[w];
}

extern "C" void kernel_launch(void* const* d_in, const int* in_sizes, int n_in,
                              void* d_out, int out_size) {
    const float* f = (const float*)d_in[0];   // [32, 64, 4096] float32
    const float* t = (const float*)d_in[1];   // [64] float32
    float4* out = (float4*)d_out;             // [32, 64, 2048] float32

    // Kernel A: 4189 table entries, 8 shifted copies
    {
        int threads = 256;
        int blocks = (TABLE_N + threads - 1) / threads;   // 17
        pp_table_kernel<<<blocks, threads>>>(f, t);
    }
    // Kernel B: 4 rows per block, 8 float4 per thread
    {
        pp_gather_kernel<<<(B_DIM * C_DIM) / 4, 256>>>(out);
    }
}